// round 11
// baseline (speedup 1.0000x reference)
#include <cuda_runtime.h>
#include <cstdint>

// LocalNorm2d: 32x32 box-filter local normalization, reflect padding.
// x: (32,3,512,512) fp32 -> out same shape.
//
// R10 = R9 (warp-private cp.async ring, no block syncs) with:
//   - pipeline deepened: NSLOT 4->8, PFD 3->6 (lead ~6 row-periods covers the
//     ~577-cycle DRAM latency that PFD=3 only partially hid)
//   - staging source is a streaming pointer (sign-flip reflection), removing
//     the per-row rmap+IMAD address build.

namespace {
constexpr int Hh    = 512;
constexpr int Ww    = 512;
constexpr int KSZ   = 32;
constexpr int PD    = 16;
constexpr int RSEG  = 64;          // output rows per warp
constexpr int NSEG  = Hh / RSEG;   // 8
constexpr int WOUT  = 96;          // output cols per warp
constexpr int NCG   = 6;           // col groups per row band
constexpr int NWPB  = 8;           // warps per block
constexpr int NT    = NWPB * 32;   // 256
constexpr int NIMG  = 32 * 3;
constexpr int NSLOT = 8;           // warp-private ring slots (power of 2)
constexpr int PFD   = 6;           // prefetch distance (rows)
}

__device__ __forceinline__ int rmap(int q) {   // reflect into [0, 511]
    q = q < 0 ? -q : q;
    return q > (Ww - 1) ? 2 * (Ww - 1) - q : q;
}

// v = (x - mean)/std on raw sums: (1024*x - S) * rsqrt(|1024*Q - S^2|)
__device__ __forceinline__ float norm1(float ws, float wq, float xc) {
    float V  = fabsf(fmaf(-ws, ws, 1024.0f * wq));
    float rs = __frsqrt_rn(fmaxf(V, 1e-12f));
    float v  = fmaf(1024.0f, xc, -ws) * rs;
    return fminf(6.0f, fmaxf(-6.0f, v));
}

// All 32 lanes: copy 16B each -> 128 floats of original row into smem slot.
__device__ __forceinline__ void stage_row(const float* __restrict__ src,
                                          float* dst_slot, int lane) {
    uint32_t d = (uint32_t)__cvta_generic_to_shared(dst_slot + lane * 4);
    asm volatile("cp.async.cg.shared.global [%0], [%1], 16;\n"
                 :: "r"(d), "l"(src + lane * 4));
    asm volatile("cp.async.commit_group;\n" ::);
}

__global__ __launch_bounds__(NT, 4)
void localnorm_kernel(const float* __restrict__ x, float* __restrict__ out)
{
    __shared__ float ring[NWPB][NSLOT][128];   // 32 KB, warp-private rows

    const int lane = threadIdx.x & 31;
    const int wrp  = threadIdx.x >> 5;
    const int g    = blockIdx.x * NWPB + wrp;    // 0..47
    const int seg  = g / NCG;                    // 0..7
    const int cg   = g - seg * NCG;              // 0..5
    const int img  = blockIdx.y;

    const float* __restrict__ xin = x   + (size_t)img * (Hh * Ww);
    float*       __restrict__ op  = out + (size_t)img * (Hh * Ww);

    const int  c0       = cg * WOUT + 4 * lane;      // padded col base
    const bool interior = (c0 >= PD && c0 <= Ww + PD - 4);
    const int  off      = interior ? (c0 - PD) : 0;

    // warp's staged window of ORIGINAL columns: [sbase, sbase+128)
    const int sbase = (cg == 0) ? 0 : ((cg == NCG - 1) ? (Ww - 128)
                                                       : (cg * WOUT - PD));
    int cm0 = 0, cm1 = 0, cm2 = 0, cm3 = 0;
    if (!interior) {
        cm0 = rmap(c0 + 0 - PD); cm1 = rmap(c0 + 1 - PD);
        cm2 = rmap(c0 + 2 - PD); cm3 = rmap(c0 + 3 - PD);
    }
    // local (in-slot) offsets
    const int loff = off - sbase;                 // interior lanes
    const int lm0 = cm0 - sbase, lm1 = cm1 - sbase;
    const int lm2 = cm2 - sbase, lm3 = cm3 - sbase;

    const int  rstart = seg * RSEG;
    const int  rend   = rstart + RSEG;
    const bool emit   = (lane < 24) && (c0 < Ww);

    float* const wring = &ring[wrp][0][0];
    const float* const psrc = xin + sbase;        // staging source base

    // ---- pre-stage incoming rows for iterations rstart..rstart+PFD-1:
    //      original rows rmap(rstart+16+k) -> slot (rstart+k)&7 ----
    #pragma unroll
    for (int k = 0; k < PFD; ++k) {
        const int rq = rmap(rstart + PD + k);     // always < 512 (max 469+)
        stage_row(psrc + (size_t)rq * Ww,
                  wring + ((rstart + k) & (NSLOT - 1)) * 128, lane);
    }

    // ---- prologue: accumulate original rows rmap(rstart-16 .. rstart+15) ----
    float s0 = 0.f, s1 = 0.f, s2 = 0.f, s3 = 0.f;
    float q0 = 0.f, q1 = 0.f, q2 = 0.f, q3 = 0.f;
    #pragma unroll 2
    for (int p = rstart; p < rstart + KSZ; ++p) {
        const float* r = xin + (size_t)rmap(p - PD) * Ww + off;
        float4 v = interior ? *reinterpret_cast<const float4*>(r)
                            : make_float4(r[cm0], r[cm1], r[cm2], r[cm3]);
        s0 += v.x; s1 += v.y; s2 += v.z; s3 += v.w;
        q0 = fmaf(v.x, v.x, q0); q1 = fmaf(v.y, v.y, q1);
        q2 = fmaf(v.z, v.z, q2); q3 = fmaf(v.w, v.w, q3);
    }

    // ---- streaming pointers ----
    const float* po = xin + (size_t)rmap(rstart - PD) * Ww + off; // row rmap(i-16)
    const float* pc = xin + (size_t)rstart * Ww + c0;             // row i (center)
    const float* ps = psrc + (size_t)rmap(rstart + PD + PFD) * Ww; // stage src
    float*       pw = op  + (size_t)rstart * Ww + c0;
    int dd = (rstart == 0) ? -Ww : Ww;
    int ds = Ww;
    const int flip_o = (rstart == 0) ? PD : 0x7fffffff;            // i == 16
    const int flip_s = (rend == Hh) ? (Hh - PD - PFD - 1)          // i == 489
                                    : 0x7fffffff;

    #pragma unroll 2
    for (int i = rstart; i < rend; ++i) {
        // cache-hot loads issued early
        float4 xo = interior ? *reinterpret_cast<const float4*>(po)
                             : make_float4(po[cm0], po[cm1], po[cm2], po[cm3]);
        float4 xc;
        if (emit) xc = *reinterpret_cast<const float4*>(pc);
        if (i == flip_o) dd = Ww;
        po += dd; pc += Ww;

        // refill: stage row rmap(i+16+PFD) into slot (i+PFD)&7
        stage_row(ps, wring + ((i + PFD) & (NSLOT - 1)) * 128, lane);
        if (i == flip_s) ds = -Ww;
        ps += ds;

        // incoming row rmap(i+16) is PFD groups back in THIS warp's queue
        asm volatile("cp.async.wait_group %0;\n" :: "n"(PFD - 1) : "memory");
        __syncwarp();
        const float* rr = wring + (i & (NSLOT - 1)) * 128;
        float4 xn = interior ? *reinterpret_cast<const float4*>(rr + loff)
                             : make_float4(rr[lm0], rr[lm1], rr[lm2], rr[lm3]);

        // ---- horizontal window via in-warp shfl segment sums ----
        float i1 = s0 + s1, i2 = i1 + s2, i3 = i2 + s3;
        float j1 = q0 + q1, j2 = j1 + q2, j3 = j2 + q3;

        float as = i3 + __shfl_down_sync(0xFFFFFFFFu, i3, 1);
        float aq = j3 + __shfl_down_sync(0xFFFFFFFFu, j3, 1);
        as += __shfl_down_sync(0xFFFFFFFFu, as, 2);
        aq += __shfl_down_sync(0xFFFFFFFFu, aq, 2);
        float T8s = as + __shfl_down_sync(0xFFFFFFFFu, as, 4);
        float T8q = aq + __shfl_down_sync(0xFFFFFFFFu, aq, 4);

        float b1s = __shfl_down_sync(0xFFFFFFFFu, s0, 8);
        float b2s = __shfl_down_sync(0xFFFFFFFFu, i1, 8);
        float b3s = __shfl_down_sync(0xFFFFFFFFu, i2, 8);
        float b1q = __shfl_down_sync(0xFFFFFFFFu, q0, 8);
        float b2q = __shfl_down_sync(0xFFFFFFFFu, j1, 8);
        float b3q = __shfl_down_sync(0xFFFFFFFFu, j2, 8);

        if (emit) {
            float4 r;
            r.x = norm1(T8s,            T8q,            xc.x);
            r.y = norm1(T8s - s0 + b1s, T8q - q0 + b1q, xc.y);
            r.z = norm1(T8s - i1 + b2s, T8q - j1 + b2q, xc.z);
            r.w = norm1(T8s - i2 + b3s, T8q - j2 + b3q, xc.w);
            *reinterpret_cast<float4*>(pw) = r;
        }
        pw += Ww;

        // ---- slide vertical window ----
        s0 += xn.x - xo.x; s1 += xn.y - xo.y;
        s2 += xn.z - xo.z; s3 += xn.w - xo.w;
        q0 = fmaf(xn.x, xn.x, q0); q0 = fmaf(-xo.x, xo.x, q0);
        q1 = fmaf(xn.y, xn.y, q1); q1 = fmaf(-xo.y, xo.y, q1);
        q2 = fmaf(xn.z, xn.z, q2); q2 = fmaf(-xo.z, xo.z, q2);
        q3 = fmaf(xn.w, xn.w, q3); q3 = fmaf(-xo.w, xo.w, q3);
    }

    // drain outstanding cp.asyncs before CTA exit (smem reuse safety)
    asm volatile("cp.async.wait_group 0;\n" ::: "memory");
}

extern "C" void kernel_launch(void* const* d_in, const int* in_sizes, int n_in,
                              void* d_out, int out_size) {
    const float* x = (const float*)d_in[0];
    float* out = (float*)d_out;
    (void)in_sizes; (void)n_in; (void)out_size;

    dim3 grid(NSEG * NCG / NWPB, NIMG);   // (6, 96) = 576 blocks
    localnorm_kernel<<<grid, NT>>>(x, out);
}

// round 12
// speedup vs baseline: 1.0116x; 1.0116x over previous
#include <cuda_runtime.h>
#include <cstdint>

// LocalNorm2d: 32x32 box-filter local normalization, reflect padding.
// x: (32,3,512,512) fp32 -> out same shape.
//
// R11 = R9 (warp-private cp.async ring, NSLOT=4/PFD=3, no block syncs) +
//   - streaming staging-source pointer (no per-row rmap/IMAD)
//   - template<EDGE_SEG>: interior row-segments (1..6) get a flip-free main
//     loop and pointer-streamed prologue; only seg 0/7 carry reflection
//     compares.

namespace {
constexpr int Hh    = 512;
constexpr int Ww    = 512;
constexpr int KSZ   = 32;
constexpr int PD    = 16;
constexpr int RSEG  = 64;          // output rows per warp
constexpr int NSEG  = Hh / RSEG;   // 8
constexpr int WOUT  = 96;          // output cols per warp
constexpr int NCG   = 6;           // col groups per row band
constexpr int NWPB  = 8;           // warps per block
constexpr int NT    = NWPB * 32;   // 256
constexpr int NIMG  = 32 * 3;
constexpr int NSLOT = 4;           // warp-private ring slots (power of 2)
constexpr int PFD   = 3;           // prefetch distance (rows)
}

__device__ __forceinline__ int rmap(int q) {   // reflect into [0, 511]
    q = q < 0 ? -q : q;
    return q > (Ww - 1) ? 2 * (Ww - 1) - q : q;
}

// v = (x - mean)/std on raw sums: (1024*x - S) * rsqrt(|1024*Q - S^2|)
__device__ __forceinline__ float norm1(float ws, float wq, float xc) {
    float V  = fabsf(fmaf(-ws, ws, 1024.0f * wq));
    float rs = __frsqrt_rn(fmaxf(V, 1e-12f));
    float v  = fmaf(1024.0f, xc, -ws) * rs;
    return fminf(6.0f, fmaxf(-6.0f, v));
}

// All 32 lanes: copy 16B each -> 128 floats of original row into smem slot.
__device__ __forceinline__ void stage_row(const float* __restrict__ src,
                                          float* dst_slot, int lane) {
    uint32_t d = (uint32_t)__cvta_generic_to_shared(dst_slot + lane * 4);
    asm volatile("cp.async.cg.shared.global [%0], [%1], 16;\n"
                 :: "r"(d), "l"(src + lane * 4));
    asm volatile("cp.async.commit_group;\n" ::);
}

template<bool EDGE_SEG>
__device__ __forceinline__ void run_seg(
    const float* __restrict__ xin, float* __restrict__ op,
    float* __restrict__ wring, int lane, int cg, int rstart)
{
    const int  c0       = cg * WOUT + 4 * lane;      // padded col base
    const bool interior = (c0 >= PD && c0 <= Ww + PD - 4);
    const int  off      = interior ? (c0 - PD) : 0;

    // warp's staged window of ORIGINAL columns: [sbase, sbase+128)
    const int sbase = (cg == 0) ? 0 : ((cg == NCG - 1) ? (Ww - 128)
                                                       : (cg * WOUT - PD));
    int cm0 = 0, cm1 = 0, cm2 = 0, cm3 = 0;
    if (!interior) {
        cm0 = rmap(c0 + 0 - PD); cm1 = rmap(c0 + 1 - PD);
        cm2 = rmap(c0 + 2 - PD); cm3 = rmap(c0 + 3 - PD);
    }
    // local (in-slot) offsets
    const int loff = off - sbase;
    const int lm0 = cm0 - sbase, lm1 = cm1 - sbase;
    const int lm2 = cm2 - sbase, lm3 = cm3 - sbase;

    const int  rend = rstart + RSEG;
    const bool emit = (lane < 24) && (c0 < Ww);
    const float* const psrc = xin + sbase;        // staging source base

    // ---- pre-stage incoming rows for iterations rstart..rstart+PFD-1 ----
    #pragma unroll
    for (int k = 0; k < PFD; ++k) {
        const int rq = rmap(rstart + PD + k);     // always <= 511 here
        stage_row(psrc + (size_t)rq * Ww,
                  wring + ((rstart + k) & (NSLOT - 1)) * 128, lane);
    }

    // ---- prologue: accumulate original rows rmap(rstart-16 .. rstart+15) ----
    float s0 = 0.f, s1 = 0.f, s2 = 0.f, s3 = 0.f;
    float q0 = 0.f, q1 = 0.f, q2 = 0.f, q3 = 0.f;
    if (EDGE_SEG) {
        #pragma unroll 2
        for (int p = rstart; p < rstart + KSZ; ++p) {
            const float* r = xin + (size_t)rmap(p - PD) * Ww + off;
            float4 v = interior ? *reinterpret_cast<const float4*>(r)
                                : make_float4(r[cm0], r[cm1], r[cm2], r[cm3]);
            s0 += v.x; s1 += v.y; s2 += v.z; s3 += v.w;
            q0 = fmaf(v.x, v.x, q0); q1 = fmaf(v.y, v.y, q1);
            q2 = fmaf(v.z, v.z, q2); q3 = fmaf(v.w, v.w, q3);
        }
    } else {
        // interior segment: rows rstart-16 .. rstart+15 need no reflection
        const float* pp = xin + (size_t)(rstart - PD) * Ww + off;
        #pragma unroll 2
        for (int p = 0; p < KSZ; ++p) {
            float4 v = interior ? *reinterpret_cast<const float4*>(pp)
                                : make_float4(pp[cm0], pp[cm1], pp[cm2], pp[cm3]);
            pp += Ww;
            s0 += v.x; s1 += v.y; s2 += v.z; s3 += v.w;
            q0 = fmaf(v.x, v.x, q0); q1 = fmaf(v.y, v.y, q1);
            q2 = fmaf(v.z, v.z, q2); q3 = fmaf(v.w, v.w, q3);
        }
    }

    // ---- streaming pointers ----
    const float* po = xin + (size_t)rmap(rstart - PD) * Ww + off;  // row rmap(i-16)
    const float* pc = xin + (size_t)rstart * Ww + c0;              // row i (center)
    const float* ps = psrc + (size_t)rmap(rstart + PD + PFD) * Ww; // stage src
    float*       pw = op  + (size_t)rstart * Ww + c0;
    int dd = (rstart == 0) ? -Ww : Ww;
    int ds = Ww;
    const int flip_o = (rstart == 0) ? PD : 0x7fffffff;            // i == 16
    const int flip_s = (rend == Hh) ? (Hh - PD - PFD - 1)          // i == 492
                                    : 0x7fffffff;

    #pragma unroll 2
    for (int i = rstart; i < rend; ++i) {
        // cache-hot loads issued early
        float4 xo = interior ? *reinterpret_cast<const float4*>(po)
                             : make_float4(po[cm0], po[cm1], po[cm2], po[cm3]);
        float4 xc;
        if (emit) xc = *reinterpret_cast<const float4*>(pc);
        pc += Ww;
        if (EDGE_SEG) {
            if (i == flip_o) dd = Ww;
            po += dd;
        } else {
            po += Ww;
        }

        // refill: stage row rmap(i+16+PFD) into slot (i+PFD)&3
        stage_row(ps, wring + ((i + PFD) & (NSLOT - 1)) * 128, lane);
        if (EDGE_SEG) {
            if (i == flip_s) ds = -Ww;
            ps += ds;
        } else {
            ps += Ww;
        }

        // incoming row rmap(i+16) is PFD groups back in THIS warp's queue
        asm volatile("cp.async.wait_group %0;\n" :: "n"(PFD - 1) : "memory");
        __syncwarp();
        const float* rr = wring + (i & (NSLOT - 1)) * 128;
        float4 xn = interior ? *reinterpret_cast<const float4*>(rr + loff)
                             : make_float4(rr[lm0], rr[lm1], rr[lm2], rr[lm3]);

        // ---- horizontal window via in-warp shfl segment sums ----
        float i1 = s0 + s1, i2 = i1 + s2, i3 = i2 + s3;
        float j1 = q0 + q1, j2 = j1 + q2, j3 = j2 + q3;

        float as = i3 + __shfl_down_sync(0xFFFFFFFFu, i3, 1);
        float aq = j3 + __shfl_down_sync(0xFFFFFFFFu, j3, 1);
        as += __shfl_down_sync(0xFFFFFFFFu, as, 2);
        aq += __shfl_down_sync(0xFFFFFFFFu, aq, 2);
        float T8s = as + __shfl_down_sync(0xFFFFFFFFu, as, 4);
        float T8q = aq + __shfl_down_sync(0xFFFFFFFFu, aq, 4);

        float b1s = __shfl_down_sync(0xFFFFFFFFu, s0, 8);
        float b2s = __shfl_down_sync(0xFFFFFFFFu, i1, 8);
        float b3s = __shfl_down_sync(0xFFFFFFFFu, i2, 8);
        float b1q = __shfl_down_sync(0xFFFFFFFFu, q0, 8);
        float b2q = __shfl_down_sync(0xFFFFFFFFu, j1, 8);
        float b3q = __shfl_down_sync(0xFFFFFFFFu, j2, 8);

        if (emit) {
            float4 r;
            r.x = norm1(T8s,            T8q,            xc.x);
            r.y = norm1(T8s - s0 + b1s, T8q - q0 + b1q, xc.y);
            r.z = norm1(T8s - i1 + b2s, T8q - j1 + b2q, xc.z);
            r.w = norm1(T8s - i2 + b3s, T8q - j2 + b3q, xc.w);
            *reinterpret_cast<float4*>(pw) = r;
        }
        pw += Ww;

        // ---- slide vertical window ----
        s0 += xn.x - xo.x; s1 += xn.y - xo.y;
        s2 += xn.z - xo.z; s3 += xn.w - xo.w;
        q0 = fmaf(xn.x, xn.x, q0); q0 = fmaf(-xo.x, xo.x, q0);
        q1 = fmaf(xn.y, xn.y, q1); q1 = fmaf(-xo.y, xo.y, q1);
        q2 = fmaf(xn.z, xn.z, q2); q2 = fmaf(-xo.z, xo.z, q2);
        q3 = fmaf(xn.w, xn.w, q3); q3 = fmaf(-xo.w, xo.w, q3);
    }
}

__global__ __launch_bounds__(NT, 4)
void localnorm_kernel(const float* __restrict__ x, float* __restrict__ out)
{
    __shared__ float ring[NWPB][NSLOT][128];   // 16 KB, warp-private rows

    const int lane = threadIdx.x & 31;
    const int wrp  = threadIdx.x >> 5;
    const int g    = blockIdx.x * NWPB + wrp;    // 0..47
    const int seg  = g / NCG;                    // 0..7
    const int cg   = g - seg * NCG;              // 0..5
    const int img  = blockIdx.y;

    const float* __restrict__ xin = x   + (size_t)img * (Hh * Ww);
    float*       __restrict__ op  = out + (size_t)img * (Hh * Ww);
    float* const wring = &ring[wrp][0][0];

    if (seg == 0 || seg == NSEG - 1) {
        run_seg<true >(xin, op, wring, lane, cg, seg * RSEG);
    } else {
        run_seg<false>(xin, op, wring, lane, cg, seg * RSEG);
    }

    // drain outstanding cp.asyncs before CTA exit (smem reuse safety)
    asm volatile("cp.async.wait_group 0;\n" ::: "memory");
}

extern "C" void kernel_launch(void* const* d_in, const int* in_sizes, int n_in,
                              void* d_out, int out_size) {
    const float* x = (const float*)d_in[0];
    float* out = (float*)d_out;
    (void)in_sizes; (void)n_in; (void)out_size;

    dim3 grid(NSEG * NCG / NWPB, NIMG);   // (6, 96) = 576 blocks
    localnorm_kernel<<<grid, NT>>>(x, out);
}

// round 13
// speedup vs baseline: 1.0163x; 1.0046x over previous
#include <cuda_runtime.h>
#include <cstdint>

// LocalNorm2d: 32x32 box-filter local normalization, reflect padding.
// x: (32,3,512,512) fp32 -> out same shape.
//
// R12 = R11 with the pipeline over-wait fixed: the refill is committed BEFORE
// the wait (pending = PFD+1 there), so the wait must be wait_group(PFD) --
// drain to the oldest group only. R10/R11 used wait_group(PFD-1) after the
// refill, silently waiting for TWO groups per row (the whole regression).
//
//   - warp-private cp.async ring (NSLOT=4, PFD=3), no block syncs
//   - each warp: 128 padded cols (4/thread) x 64 output rows
//   - streaming pointers everywhere; reflection = stride sign flip
//   - template<EDGE_SEG>: interior row segments have flip-free loops
//   - horizontal 32-window via in-warp shfl segment sums

namespace {
constexpr int Hh    = 512;
constexpr int Ww    = 512;
constexpr int KSZ   = 32;
constexpr int PD    = 16;
constexpr int RSEG  = 64;          // output rows per warp
constexpr int NSEG  = Hh / RSEG;   // 8
constexpr int WOUT  = 96;          // output cols per warp
constexpr int NCG   = 6;           // col groups per row band
constexpr int NWPB  = 8;           // warps per block
constexpr int NT    = NWPB * 32;   // 256
constexpr int NIMG  = 32 * 3;
constexpr int NSLOT = 4;           // warp-private ring slots (power of 2)
constexpr int PFD   = 3;           // prefetch distance (rows)
}

__device__ __forceinline__ int rmap(int q) {   // reflect into [0, 511]
    q = q < 0 ? -q : q;
    return q > (Ww - 1) ? 2 * (Ww - 1) - q : q;
}

// v = (x - mean)/std on raw sums: (1024*x - S) * rsqrt(|1024*Q - S^2|)
__device__ __forceinline__ float norm1(float ws, float wq, float xc) {
    float V  = fabsf(fmaf(-ws, ws, 1024.0f * wq));
    float rs = __frsqrt_rn(fmaxf(V, 1e-12f));
    float v  = fmaf(1024.0f, xc, -ws) * rs;
    return fminf(6.0f, fmaxf(-6.0f, v));
}

// All 32 lanes: copy 16B each -> 128 floats of original row into smem slot.
__device__ __forceinline__ void stage_row(const float* __restrict__ src,
                                          float* dst_slot, int lane) {
    uint32_t d = (uint32_t)__cvta_generic_to_shared(dst_slot + lane * 4);
    asm volatile("cp.async.cg.shared.global [%0], [%1], 16;\n"
                 :: "r"(d), "l"(src + lane * 4));
    asm volatile("cp.async.commit_group;\n" ::);
}

template<bool EDGE_SEG>
__device__ __forceinline__ void run_seg(
    const float* __restrict__ xin, float* __restrict__ op,
    float* __restrict__ wring, int lane, int cg, int rstart)
{
    const int  c0       = cg * WOUT + 4 * lane;      // padded col base
    const bool interior = (c0 >= PD && c0 <= Ww + PD - 4);
    const int  off      = interior ? (c0 - PD) : 0;

    // warp's staged window of ORIGINAL columns: [sbase, sbase+128)
    const int sbase = (cg == 0) ? 0 : ((cg == NCG - 1) ? (Ww - 128)
                                                       : (cg * WOUT - PD));
    int cm0 = 0, cm1 = 0, cm2 = 0, cm3 = 0;
    if (!interior) {
        cm0 = rmap(c0 + 0 - PD); cm1 = rmap(c0 + 1 - PD);
        cm2 = rmap(c0 + 2 - PD); cm3 = rmap(c0 + 3 - PD);
    }
    // local (in-slot) offsets
    const int loff = off - sbase;
    const int lm0 = cm0 - sbase, lm1 = cm1 - sbase;
    const int lm2 = cm2 - sbase, lm3 = cm3 - sbase;

    const int  rend = rstart + RSEG;
    const bool emit = (lane < 24) && (c0 < Ww);
    const float* const psrc = xin + sbase;        // staging source base

    // ---- pre-stage incoming rows for iterations rstart..rstart+PFD-1 ----
    #pragma unroll
    for (int k = 0; k < PFD; ++k) {
        const int rq = rmap(rstart + PD + k);
        stage_row(psrc + (size_t)rq * Ww,
                  wring + ((rstart + k) & (NSLOT - 1)) * 128, lane);
    }

    // ---- prologue: accumulate original rows rmap(rstart-16 .. rstart+15) ----
    float s0 = 0.f, s1 = 0.f, s2 = 0.f, s3 = 0.f;
    float q0 = 0.f, q1 = 0.f, q2 = 0.f, q3 = 0.f;
    if (EDGE_SEG) {
        #pragma unroll 2
        for (int p = rstart; p < rstart + KSZ; ++p) {
            const float* r = xin + (size_t)rmap(p - PD) * Ww + off;
            float4 v = interior ? *reinterpret_cast<const float4*>(r)
                                : make_float4(r[cm0], r[cm1], r[cm2], r[cm3]);
            s0 += v.x; s1 += v.y; s2 += v.z; s3 += v.w;
            q0 = fmaf(v.x, v.x, q0); q1 = fmaf(v.y, v.y, q1);
            q2 = fmaf(v.z, v.z, q2); q3 = fmaf(v.w, v.w, q3);
        }
    } else {
        const float* pp = xin + (size_t)(rstart - PD) * Ww + off;
        #pragma unroll 2
        for (int p = 0; p < KSZ; ++p) {
            float4 v = interior ? *reinterpret_cast<const float4*>(pp)
                                : make_float4(pp[cm0], pp[cm1], pp[cm2], pp[cm3]);
            pp += Ww;
            s0 += v.x; s1 += v.y; s2 += v.z; s3 += v.w;
            q0 = fmaf(v.x, v.x, q0); q1 = fmaf(v.y, v.y, q1);
            q2 = fmaf(v.z, v.z, q2); q3 = fmaf(v.w, v.w, q3);
        }
    }

    // ---- streaming pointers ----
    const float* po = xin + (size_t)rmap(rstart - PD) * Ww + off;  // row rmap(i-16)
    const float* pc = xin + (size_t)rstart * Ww + c0;              // row i (center)
    const float* ps = psrc + (size_t)rmap(rstart + PD + PFD) * Ww; // stage src
    float*       pw = op  + (size_t)rstart * Ww + c0;
    int dd = (rstart == 0) ? -Ww : Ww;
    int ds = Ww;
    const int flip_o = (rstart == 0) ? PD : 0x7fffffff;            // i == 16
    const int flip_s = (rend == Hh) ? (Hh - PD - PFD - 1)          // i == 492
                                    : 0x7fffffff;

    #pragma unroll 2
    for (int i = rstart; i < rend; ++i) {
        // cache-hot loads issued early
        float4 xo = interior ? *reinterpret_cast<const float4*>(po)
                             : make_float4(po[cm0], po[cm1], po[cm2], po[cm3]);
        float4 xc;
        if (emit) xc = *reinterpret_cast<const float4*>(pc);
        pc += Ww;
        if (EDGE_SEG) {
            if (i == flip_o) dd = Ww;
            po += dd;
        } else {
            po += Ww;
        }

        // refill: stage row rmap(i+16+PFD) into slot (i+PFD)&3
        stage_row(ps, wring + ((i + PFD) & (NSLOT - 1)) * 128, lane);
        if (EDGE_SEG) {
            if (i == flip_s) ds = -Ww;
            ps += ds;
        } else {
            ps += Ww;
        }

        // pending groups here = PFD+1 (refill just committed) -> drain to
        // PFD pending, i.e. wait ONLY for the oldest group (row i's slot).
        asm volatile("cp.async.wait_group %0;\n" :: "n"(PFD) : "memory");
        __syncwarp();
        const float* rr = wring + (i & (NSLOT - 1)) * 128;
        float4 xn = interior ? *reinterpret_cast<const float4*>(rr + loff)
                             : make_float4(rr[lm0], rr[lm1], rr[lm2], rr[lm3]);

        // ---- horizontal window via in-warp shfl segment sums ----
        float i1 = s0 + s1, i2 = i1 + s2, i3 = i2 + s3;
        float j1 = q0 + q1, j2 = j1 + q2, j3 = j2 + q3;

        float as = i3 + __shfl_down_sync(0xFFFFFFFFu, i3, 1);
        float aq = j3 + __shfl_down_sync(0xFFFFFFFFu, j3, 1);
        as += __shfl_down_sync(0xFFFFFFFFu, as, 2);
        aq += __shfl_down_sync(0xFFFFFFFFu, aq, 2);
        float T8s = as + __shfl_down_sync(0xFFFFFFFFu, as, 4);
        float T8q = aq + __shfl_down_sync(0xFFFFFFFFu, aq, 4);

        float b1s = __shfl_down_sync(0xFFFFFFFFu, s0, 8);
        float b2s = __shfl_down_sync(0xFFFFFFFFu, i1, 8);
        float b3s = __shfl_down_sync(0xFFFFFFFFu, i2, 8);
        float b1q = __shfl_down_sync(0xFFFFFFFFu, q0, 8);
        float b2q = __shfl_down_sync(0xFFFFFFFFu, j1, 8);
        float b3q = __shfl_down_sync(0xFFFFFFFFu, j2, 8);

        if (emit) {
            float4 r;
            r.x = norm1(T8s,            T8q,            xc.x);
            r.y = norm1(T8s - s0 + b1s, T8q - q0 + b1q, xc.y);
            r.z = norm1(T8s - i1 + b2s, T8q - j1 + b2q, xc.z);
            r.w = norm1(T8s - i2 + b3s, T8q - j2 + b3q, xc.w);
            *reinterpret_cast<float4*>(pw) = r;
        }
        pw += Ww;

        // ---- slide vertical window ----
        s0 += xn.x - xo.x; s1 += xn.y - xo.y;
        s2 += xn.z - xo.z; s3 += xn.w - xo.w;
        q0 = fmaf(xn.x, xn.x, q0); q0 = fmaf(-xo.x, xo.x, q0);
        q1 = fmaf(xn.y, xn.y, q1); q1 = fmaf(-xo.y, xo.y, q1);
        q2 = fmaf(xn.z, xn.z, q2); q2 = fmaf(-xo.z, xo.z, q2);
        q3 = fmaf(xn.w, xn.w, q3); q3 = fmaf(-xo.w, xo.w, q3);
    }
}

__global__ __launch_bounds__(NT, 4)
void localnorm_kernel(const float* __restrict__ x, float* __restrict__ out)
{
    __shared__ float ring[NWPB][NSLOT][128];   // 16 KB, warp-private rows

    const int lane = threadIdx.x & 31;
    const int wrp  = threadIdx.x >> 5;
    const int g    = blockIdx.x * NWPB + wrp;    // 0..47
    const int seg  = g / NCG;                    // 0..7
    const int cg   = g - seg * NCG;              // 0..5
    const int img  = blockIdx.y;

    const float* __restrict__ xin = x   + (size_t)img * (Hh * Ww);
    float*       __restrict__ op  = out + (size_t)img * (Hh * Ww);
    float* const wring = &ring[wrp][0][0];

    if (seg == 0 || seg == NSEG - 1) {
        run_seg<true >(xin, op, wring, lane, cg, seg * RSEG);
    } else {
        run_seg<false>(xin, op, wring, lane, cg, seg * RSEG);
    }

    // drain outstanding cp.asyncs before CTA exit (smem reuse safety)
    asm volatile("cp.async.wait_group 0;\n" ::: "memory");
}

extern "C" void kernel_launch(void* const* d_in, const int* in_sizes, int n_in,
                              void* d_out, int out_size) {
    const float* x = (const float*)d_in[0];
    float* out = (float*)d_out;
    (void)in_sizes; (void)n_in; (void)out_size;

    dim3 grid(NSEG * NCG / NWPB, NIMG);   // (6, 96) = 576 blocks
    localnorm_kernel<<<grid, NT>>>(x, out);
}

// round 14
// speedup vs baseline: 1.0782x; 1.0610x over previous
#include <cuda_runtime.h>
#include <cstdint>

// LocalNorm2d: 32x32 box-filter local normalization, reflect padding.
// x: (32,3,512,512) fp32 -> out same shape.
//
// R13 = R9 VERBATIM (the 88.6us winner: warp-private cp.async ring,
// NSLOT=4/PFD=3, wait-then-refill order, per-row staging rmap, no block
// syncs) + L2 residency policies:
//   - staged xn lines: L2::evict_last  (2 future reads: xc @ +16, xo @ +32)
//   - output stores:   L2::evict_first (never re-read; stop write pollution)
// Goal: keep the 76MB chip-wide reuse window resident in the 126MB L2 so the
// xo/xc streams are guaranteed L2 hits.

namespace {
constexpr int Hh    = 512;
constexpr int Ww    = 512;
constexpr int KSZ   = 32;
constexpr int PD    = 16;
constexpr int RSEG  = 64;          // output rows per warp
constexpr int NSEG  = Hh / RSEG;   // 8
constexpr int WOUT  = 96;          // output cols per warp
constexpr int NCG   = 6;           // col groups per row band
constexpr int NWPB  = 8;           // warps per block
constexpr int NT    = NWPB * 32;   // 256
constexpr int NIMG  = 32 * 3;
constexpr int NSLOT = 4;           // warp-private ring slots (power of 2)
constexpr int PFD   = 3;           // prefetch distance (rows)
}

__device__ __forceinline__ int rmap(int q) {   // reflect into [0, 511]
    q = q < 0 ? -q : q;
    return q > (Ww - 1) ? 2 * (Ww - 1) - q : q;
}

// v = (x - mean)/std on raw sums: (1024*x - S) * rsqrt(|1024*Q - S^2|)
__device__ __forceinline__ float norm1(float ws, float wq, float xc) {
    float V  = fabsf(fmaf(-ws, ws, 1024.0f * wq));
    float rs = __frsqrt_rn(fmaxf(V, 1e-12f));
    float v  = fmaf(1024.0f, xc, -ws) * rs;
    return fminf(6.0f, fmaxf(-6.0f, v));
}

// All 32 lanes: copy 16B each -> 128 floats of original row into smem slot.
// Staged lines marked evict_last: they are re-read twice (xc, xo).
__device__ __forceinline__ void stage_row(const float* __restrict__ srcbase,
                                          float* dst_slot, int lane,
                                          uint64_t pol_last) {
    uint32_t d = (uint32_t)__cvta_generic_to_shared(dst_slot + lane * 4);
    asm volatile("cp.async.cg.shared.global.L2::cache_hint [%0], [%1], 16, %2;\n"
                 :: "r"(d), "l"(srcbase + lane * 4), "l"(pol_last));
    asm volatile("cp.async.commit_group;\n" ::);
}

__global__ __launch_bounds__(NT, 4)
void localnorm_kernel(const float* __restrict__ x, float* __restrict__ out)
{
    __shared__ float ring[NWPB][NSLOT][128];   // 16 KB, warp-private rows

    const int lane = threadIdx.x & 31;
    const int wrp  = threadIdx.x >> 5;
    const int g    = blockIdx.x * NWPB + wrp;    // 0..47
    const int seg  = g / NCG;                    // 0..7
    const int cg   = g - seg * NCG;              // 0..5
    const int img  = blockIdx.y;

    // L2 access policies (uniform, created once)
    uint64_t pol_last, pol_first;
    asm volatile("createpolicy.fractional.L2::evict_last.b64 %0, 1.0;"
                 : "=l"(pol_last));
    asm volatile("createpolicy.fractional.L2::evict_first.b64 %0, 1.0;"
                 : "=l"(pol_first));

    const float* __restrict__ xin = x   + (size_t)img * (Hh * Ww);
    float*       __restrict__ op  = out + (size_t)img * (Hh * Ww);

    const int  c0       = cg * WOUT + 4 * lane;      // padded col base
    const bool interior = (c0 >= PD && c0 <= Ww + PD - 4);
    const int  off      = interior ? (c0 - PD) : 0;

    // warp's staged window of ORIGINAL columns: [sbase, sbase+128)
    const int sbase = (cg == 0) ? 0 : ((cg == NCG - 1) ? (Ww - 128)
                                                       : (cg * WOUT - PD));
    int cm0 = 0, cm1 = 0, cm2 = 0, cm3 = 0;
    if (!interior) {
        cm0 = rmap(c0 + 0 - PD); cm1 = rmap(c0 + 1 - PD);
        cm2 = rmap(c0 + 2 - PD); cm3 = rmap(c0 + 3 - PD);
    }
    // local (in-slot) offsets
    const int loff = off - sbase;                 // interior lanes
    const int lm0 = cm0 - sbase, lm1 = cm1 - sbase;
    const int lm2 = cm2 - sbase, lm3 = cm3 - sbase;

    const int  rstart = seg * RSEG;
    const int  rend   = rstart + RSEG;
    const bool emit   = (lane < 24) && (c0 < Ww);

    float* const wring = &ring[wrp][0][0];
    const float* const psrc = xin + sbase;        // staging source base

    // ---- pre-stage incoming rows for iterations rstart..rstart+2:
    //      original rows rmap(rstart+16+k) -> slot (rstart+k)&3 ----
    #pragma unroll
    for (int k = 0; k < PFD; ++k) {
        const int rq = rmap(rstart + PD + k);
        stage_row(psrc + (size_t)rq * Ww,
                  wring + ((rstart + k) & 3) * 128, lane, pol_last);
    }

    // ---- prologue: accumulate original rows rmap(rstart-16 .. rstart+15) ----
    float s0 = 0.f, s1 = 0.f, s2 = 0.f, s3 = 0.f;
    float q0 = 0.f, q1 = 0.f, q2 = 0.f, q3 = 0.f;
    #pragma unroll 2
    for (int p = rstart; p < rstart + KSZ; ++p) {
        const float* r = xin + (size_t)rmap(p - PD) * Ww + off;
        float4 v = interior ? *reinterpret_cast<const float4*>(r)
                            : make_float4(r[cm0], r[cm1], r[cm2], r[cm3]);
        s0 += v.x; s1 += v.y; s2 += v.z; s3 += v.w;
        q0 = fmaf(v.x, v.x, q0); q1 = fmaf(v.y, v.y, q1);
        q2 = fmaf(v.z, v.z, q2); q3 = fmaf(v.w, v.w, q3);
    }

    // ---- streaming pointers for the cache-hot streams ----
    const float* po = xin + (size_t)rmap(rstart - PD) * Ww + off; // row rmap(i-16)
    const float* pc = xin + (size_t)rstart * Ww + c0;             // row i (center)
    float*       pw = op  + (size_t)rstart * Ww + c0;
    int dd = (rstart == 0) ? -Ww : Ww;
    const int flip_o = (rstart == 0) ? PD : 0x7fffffff;           // i == 16

    #pragma unroll 2
    for (int i = rstart; i < rend; ++i) {
        // cache-hot loads issued early
        float4 xo = interior ? *reinterpret_cast<const float4*>(po)
                             : make_float4(po[cm0], po[cm1], po[cm2], po[cm3]);
        float4 xc;
        if (emit) xc = *reinterpret_cast<const float4*>(pc);
        if (i == flip_o) dd = Ww;
        po += dd; pc += Ww;

        // incoming row rmap(i+16) is PFD groups back in THIS warp's queue
        asm volatile("cp.async.wait_group %0;\n" :: "n"(PFD - 1) : "memory");
        __syncwarp();
        const float* rr = wring + (i & 3) * 128;
        float4 xn = interior ? *reinterpret_cast<const float4*>(rr + loff)
                             : make_float4(rr[lm0], rr[lm1], rr[lm2], rr[lm3]);

        // refill: stage original row rmap(i+16+PFD) into slot (i+PFD)&3
        {
            const int rq = rmap(i + PD + PFD);
            stage_row(psrc + (size_t)rq * Ww,
                      wring + ((i + PFD) & 3) * 128, lane, pol_last);
        }

        // ---- horizontal window via in-warp shfl segment sums ----
        float i1 = s0 + s1, i2 = i1 + s2, i3 = i2 + s3;
        float j1 = q0 + q1, j2 = j1 + q2, j3 = j2 + q3;

        float as = i3 + __shfl_down_sync(0xFFFFFFFFu, i3, 1);
        float aq = j3 + __shfl_down_sync(0xFFFFFFFFu, j3, 1);
        as += __shfl_down_sync(0xFFFFFFFFu, as, 2);
        aq += __shfl_down_sync(0xFFFFFFFFu, aq, 2);
        float T8s = as + __shfl_down_sync(0xFFFFFFFFu, as, 4);
        float T8q = aq + __shfl_down_sync(0xFFFFFFFFu, aq, 4);

        float b1s = __shfl_down_sync(0xFFFFFFFFu, s0, 8);
        float b2s = __shfl_down_sync(0xFFFFFFFFu, i1, 8);
        float b3s = __shfl_down_sync(0xFFFFFFFFu, i2, 8);
        float b1q = __shfl_down_sync(0xFFFFFFFFu, q0, 8);
        float b2q = __shfl_down_sync(0xFFFFFFFFu, j1, 8);
        float b3q = __shfl_down_sync(0xFFFFFFFFu, j2, 8);

        if (emit) {
            float4 r;
            r.x = norm1(T8s,            T8q,            xc.x);
            r.y = norm1(T8s - s0 + b1s, T8q - q0 + b1q, xc.y);
            r.z = norm1(T8s - i1 + b2s, T8q - j1 + b2q, xc.z);
            r.w = norm1(T8s - i2 + b3s, T8q - j2 + b3q, xc.w);
            // output never re-read: evict_first keeps L2 for the reuse window
            asm volatile(
                "st.global.L2::cache_hint.v4.f32 [%0], {%1,%2,%3,%4}, %5;\n"
                :: "l"(pw), "f"(r.x), "f"(r.y), "f"(r.z), "f"(r.w),
                   "l"(pol_first) : "memory");
        }
        pw += Ww;

        // ---- slide vertical window ----
        s0 += xn.x - xo.x; s1 += xn.y - xo.y;
        s2 += xn.z - xo.z; s3 += xn.w - xo.w;
        q0 = fmaf(xn.x, xn.x, q0); q0 = fmaf(-xo.x, xo.x, q0);
        q1 = fmaf(xn.y, xn.y, q1); q1 = fmaf(-xo.y, xo.y, q1);
        q2 = fmaf(xn.z, xn.z, q2); q2 = fmaf(-xo.z, xo.z, q2);
        q3 = fmaf(xn.w, xn.w, q3); q3 = fmaf(-xo.w, xo.w, q3);
    }

    // drain outstanding cp.asyncs before CTA exit (smem reuse safety)
    asm volatile("cp.async.wait_group 0;\n" ::: "memory");
}

extern "C" void kernel_launch(void* const* d_in, const int* in_sizes, int n_in,
                              void* d_out, int out_size) {
    const float* x = (const float*)d_in[0];
    float* out = (float*)d_out;
    (void)in_sizes; (void)n_in; (void)out_size;

    dim3 grid(NSEG * NCG / NWPB, NIMG);   // (6, 96) = 576 blocks
    localnorm_kernel<<<grid, NT>>>(x, out);
}